// round 5
// baseline (speedup 1.0000x reference)
#include <cuda_runtime.h>

#define B_ 256
#define T_ 1024
#define K_ 128

__device__ float g_denom[B_];
__device__ float g_num[B_];

typedef unsigned long long u64;

// packed fp32x2 helpers (Blackwell f32x2 pipe). Two adjacent floats in memory
// are bitwise a packed f32x2, so shared-mem v2.u64 loads feed these directly.
__device__ __forceinline__ void ffma2(u64 &d, u64 a, u64 b) {
    asm("fma.rn.f32x2 %0, %1, %2, %0;" : "+l"(d) : "l"(a), "l"(b));
}
__device__ __forceinline__ u64 fadd2(u64 a, u64 b) {
    u64 r; asm("add.rn.f32x2 %0, %1, %2;" : "=l"(r) : "l"(a), "l"(b)); return r;
}
__device__ __forceinline__ u64 pack2(float lo, float hi) {
    u64 r; asm("mov.b64 %0, {%1, %2};" : "=l"(r) : "f"(lo), "f"(hi)); return r;
}
__device__ __forceinline__ void unpack2(u64 v, float &lo, float &hi) {
    asm("mov.b64 {%0, %1}, %2;" : "=f"(lo), "=f"(hi) : "l"(v));
}

// ---------------------------------------------------------------------------
// Forward algorithm, exponential domain, split-i:
//   256 threads/block. Lane pair (2j, 2j+1) owns state j; half h = tid&1
//   accumulates i in [64h, 64h+64) with packed f32x2 FMAs, halves combine via
//   shfl_xor(1). Double-buffered shared p-vector, ONE barrier per step.
// ---------------------------------------------------------------------------
__global__ void __launch_bounds__(256, 2) forward_kernel(
    const float* inp, const float* trans, const int* mask) {
    const int b   = blockIdx.x;
    const int tid = threadIdx.x;
    const int j   = tid >> 1;          // output state 0..127
    const int h   = tid & 1;           // i-half

    __shared__ __align__(16) float pbuf[2][K_];

    // E2[m] = pack(E[i], E[i+1]) for i = 64h + 2m, column j.
    u64 E2[32];
#pragma unroll
    for (int m = 0; m < 32; m++) {
        const int i = (h << 6) + 2 * m;
        E2[m] = pack2(__expf(trans[i * K_ + j]),
                      __expf(trans[(i + 1) * K_ + j]));
    }

    const float* eb = inp  + (size_t)b * T_ * K_;
    const int*   mb = mask + (size_t)b * T_;

    if (h == 0) pbuf[0][j] = __expf(eb[j]);   // t = 0
    float C = 0.0f;
    __syncthreads();

    int cur = 0;
    float e_next = eb[K_ + j];
    int   m_next = mb[1];

    for (int t = 1; t < T_; t++) {
        const float e_cur = e_next;
        const int   mc    = m_next;
        if (t + 1 < T_) {
            e_next = eb[(size_t)(t + 1) * K_ + j];
            m_next = mb[t + 1];
        }

        const float p0  = pbuf[cur][0];
        const float lp0 = __logf(p0);
        // my half of p, as packed f32x2 pairs (16B aligned: h*256 bytes)
        const ulonglong2* pv = (const ulonglong2*)(pbuf[cur] + (h << 6));

        u64 acc[8];
#pragma unroll
        for (int q = 0; q < 8; q++) acc[q] = 0ULL;
#pragma unroll
        for (int k = 0; k < 16; k++) {
            const ulonglong2 u = pv[k];                  // p[64h+4k .. +3]
            ffma2(acc[(2 * k)     & 7], u.x, E2[2 * k]);
            ffma2(acc[(2 * k + 1) & 7], u.y, E2[2 * k + 1]);
        }
        const u64 r = fadd2(fadd2(fadd2(acc[0], acc[1]), fadd2(acc[2], acc[3])),
                            fadd2(fadd2(acc[4], acc[5]), fadd2(acc[6], acc[7])));
        float lo, hi; unpack2(r, lo, hi);
        const float part = lo + hi;                       // sum over my half
        const float s = part + __shfl_xor_sync(0xffffffffu, part, 1);

        const float pn   = s * __expf(e_cur - lp0);
        const float pold = pbuf[cur][j];
        const float pnew = mc ? pn : pold;                // masked: carry p
        if (mc) C += lp0;

        cur ^= 1;
        if (h == 0) pbuf[cur][j] = pnew;
        __syncthreads();                                  // one barrier/step
    }

    if (tid == 0) {
        float sum = 0.0f;                                 // fixed order
        for (int i = 0; i < K_; i++) sum += pbuf[cur][i];
        g_denom[b] = C + __logf(sum);
    }
}

// ---------------------------------------------------------------------------
// Joint (numerator) score. One block per batch, 128 threads strided over t.
// ---------------------------------------------------------------------------
__global__ void numerator_kernel(const float* inp, const float* trans,
                                 const int* tags, const int* mask) {
    const int b   = blockIdx.x;
    const int tid = threadIdx.x;       // 128
    const int*   tb = tags + (size_t)b * T_;
    const int*   mb = mask + (size_t)b * T_;
    const float* eb = inp  + (size_t)b * T_ * K_;

    float s = 0.0f;
    int msum = 0;
    for (int t = tid; t < T_; t += 128) {
        msum += mb[t];
        if (t < T_ - 1) {
            const int tg  = tb[t]     & (K_ - 1);
            const int tg1 = tb[t + 1] & (K_ - 1);
            s += trans[tg * K_ + tg1] * (float)mb[t + 1]
               + eb[(size_t)t * K_ + tg] * (float)mb[t];
        }
    }

    __shared__ float sf[128];
    __shared__ int   si[128];
    sf[tid] = s; si[tid] = msum;
    __syncthreads();
    for (int off = 64; off > 0; off >>= 1) {
        if (tid < off) { sf[tid] += sf[tid + off]; si[tid] += si[tid + off]; }
        __syncthreads();
    }
    if (tid == 0) {
        int last_idx = si[0] - 1;
        if (last_idx < 0)   last_idx = 0;
        if (last_idx >= T_) last_idx = T_ - 1;
        const int lt = tb[last_idx] & (K_ - 1);
        g_num[b] = sf[0]
                 + eb[(size_t)(T_ - 1) * K_ + lt] * (float)mb[T_ - 1];
    }
}

// ---------------------------------------------------------------------------
__global__ void final_kernel(float* out) {
    __shared__ float sd[B_];
    const int t = threadIdx.x;
    sd[t] = g_num[t] - g_denom[t];
    __syncthreads();
    for (int off = 128; off > 0; off >>= 1) {
        if (t < off) sd[t] += sd[t + off];
        __syncthreads();
    }
    if (t == 0) out[0] = sd[0];
}

// ---------------------------------------------------------------------------
extern "C" void kernel_launch(void* const* d_in, const int* in_sizes, int n_in,
                              void* d_out, int out_size) {
    const float* inp   = (const float*)d_in[0];   // (B,T,K) f32
    const float* trans = (const float*)d_in[1];   // (K,K)   f32
    const int*   tags  = (const int*)d_in[2];     // (B,T)   i32
    const int*   mask  = (const int*)d_in[3];     // (B,T)   i32
    float* out = (float*)d_out;

    forward_kernel<<<B_, 256>>>(inp, trans, mask);
    numerator_kernel<<<B_, 128>>>(inp, trans, tags, mask);
    final_kernel<<<1, B_>>>(out);
}